// round 15
// baseline (speedup 1.0000x reference)
#include <cuda_runtime.h>
#include <cuda_fp16.h>
#include <math.h>
#include <stdint.h>

#define HH 128
#define WW 128
#define CIN 64
#define COUT 64
#define BB 2
#define KT 9
#define HW (HH*WW)
#define PADB 144   // padded A/W row stride in bytes (72 fp16) — conflict-free ldmatrix

// ---------------- scratch (device globals; no allocation) ----------------
__device__ __align__(16) float g_offy[BB * KT * HW];
__device__ __align__(16) float g_offx[BB * KT * HW];
__device__ __align__(16) float g_mask[BB * KT * HW];
__device__ __align__(16) __half g_xh16[BB * HW * CIN];        // NHWC fp16
__device__ __align__(16) __half g_wh16[KT * COUT * CIN];      // main W [k][o][c] fp16 (BN folded)
__device__ __align__(16) __half g_woh16[KT * 32 * CIN];       // offset W [k][oc pad32][c] fp16
__device__ float g_bias2[COUT];

// ---------------- helpers ----------------
__device__ __forceinline__ uint32_t smem_u32(const void* p) {
    uint32_t a;
    asm("{ .reg .u64 t; cvta.to.shared.u64 t, %1; cvt.u32.u64 %0, t; }" : "=r"(a) : "l"(p));
    return a;
}
__device__ __forceinline__ void ldm_x4(uint32_t& r0, uint32_t& r1, uint32_t& r2, uint32_t& r3,
                                       uint32_t addr) {
    asm volatile("ldmatrix.sync.aligned.m8n8.x4.shared.b16 {%0,%1,%2,%3}, [%4];"
        : "=r"(r0), "=r"(r1), "=r"(r2), "=r"(r3) : "r"(addr));
}
__device__ __forceinline__ void ldm_x2(uint32_t& r0, uint32_t& r1, uint32_t addr) {
    asm volatile("ldmatrix.sync.aligned.m8n8.x2.shared.b16 {%0,%1}, [%2];"
        : "=r"(r0), "=r"(r1) : "r"(addr));
}
__device__ __forceinline__ void mma16816(float* d,
                                         uint32_t a0, uint32_t a1, uint32_t a2, uint32_t a3,
                                         uint32_t b0, uint32_t b1) {
    asm volatile(
        "mma.sync.aligned.m16n8k16.row.col.f32.f16.f16.f32 "
        "{%0,%1,%2,%3}, {%4,%5,%6,%7}, {%8,%9}, {%0,%1,%2,%3};"
        : "+f"(d[0]), "+f"(d[1]), "+f"(d[2]), "+f"(d[3])
        : "r"(a0), "r"(a1), "r"(a2), "r"(a3), "r"(b0), "r"(b1));
}
__device__ __forceinline__ void cp_async16(uint32_t dst, const void* src) {
    asm volatile(
        "{ .reg .u64 g; cvta.to.global.u64 g, %1;\n\t"
        "cp.async.ca.shared.global [%0], [g], 16; }"
        :: "r"(dst), "l"(src) : "memory");
}
__device__ __forceinline__ void cp_async_wait_all() {
    asm volatile("cp.async.commit_group;\n\tcp.async.wait_group 0;" ::: "memory");
}

// ---------------- prep: fold BN; fp16 weight tiles ----------------
__global__ void prep_kernel(const float* __restrict__ weight,
                            const float* __restrict__ bias,
                            const float* __restrict__ gamma,
                            const float* __restrict__ beta,
                            const float* __restrict__ run_mean,
                            const float* __restrict__ run_var,
                            const float* __restrict__ w_off) {
    int idx = blockIdx.x * blockDim.x + threadIdx.x;
    if (idx < COUT) {
        float inv = gamma[idx] * rsqrtf(run_var[idx] + 1e-5f);
        g_bias2[idx] = (bias[idx] - run_mean[idx]) * inv + beta[idx];
    }
    if (idx < KT * CIN * COUT) {
        int k = idx >> 12;
        int c = (idx >> 6) & 63;
        int o = idx & 63;
        float inv = gamma[o] * rsqrtf(run_var[o] + 1e-5f);
        float val = weight[(o * CIN + c) * KT + k] * inv;
        g_wh16[k * 4096 + o * 64 + c] = __float2half_rn(val);
    }
    if (idx < KT * 32 * CIN) {
        int k = idx >> 11;
        int o = (idx >> 6) & 31;
        int c = idx & 63;
        float val = (o < 27) ? w_off[(o * CIN + c) * KT + k] : 0.0f;
        g_woh16[idx] = __float2half_rn(val);
    }
}

// ---------------- transpose x: NCHW fp32 -> NHWC fp16 ----------------
__global__ void transpose_kernel(const float* __restrict__ x) {
    __shared__ float t[32][33];
    int bid = blockIdx.x;
    int ct = bid & 1;
    int pt = (bid >> 1) & 511;
    int b = bid >> 10;
    int c0 = ct * 32, p0 = pt * 32;
    int tid = threadIdx.x;

#pragma unroll
    for (int pass = 0; pass < 4; ++pass) {
        int cl = (tid >> 5) + pass * 8;
        t[cl][tid & 31] = x[(b * CIN + c0 + cl) * HW + p0 + (tid & 31)];
    }
    __syncthreads();
    int p = tid >> 3, cc = tid & 7;
    float4 v = make_float4(t[cc * 4 + 0][p], t[cc * 4 + 1][p],
                           t[cc * 4 + 2][p], t[cc * 4 + 3][p]);
    int base = (b * HW + p0 + p) * CIN + c0 + cc * 4;
    __half2 h01 = __floats2half2_rn(v.x, v.y);
    __half2 h23 = __floats2half2_rn(v.z, v.w);
    uint2 hv;
    hv.x = *(uint32_t*)&h01;
    hv.y = *(uint32_t*)&h23;
    *(uint2*)&g_xh16[base] = hv;
}

// ---------------- offset conv as mma GEMM (fp16, single-pass W) ----------------
#define OSM_A     0
#define OSM_WH    18432
#define OSM_TOTAL 23040

__global__ void __launch_bounds__(256) offset_mma_kernel(const float* __restrict__ boff) {
    extern __shared__ char sm[];
    uint32_t smb = smem_u32(sm);
    int tid = threadIdx.x;
    int wid = tid >> 5;
    int lane = tid & 31;

    int b = blockIdx.x >> 7;
    int row = blockIdx.x & 127;

    float acc[4][4];
#pragma unroll
    for (int nt = 0; nt < 4; ++nt)
#pragma unroll
        for (int i = 0; i < 4; ++i) acc[nt][i] = 0.0f;

    uint32_t a_off = (uint32_t)((wid * 16 + (lane & 15)) * PADB + (lane >> 4) * 16);
    int l15 = lane & 15;
    uint32_t b_offv[4];
#pragma unroll
    for (int nt = 0; nt < 4; ++nt)
        b_offv[nt] = (uint32_t)((nt * 8 + (l15 & 7)) * PADB + ((l15 >> 3) & 1) * 16);

#pragma unroll 1
    for (int k = 0; k < KT; ++k) {
        int ty = k / 3, tx = k % 3;
        int rr = row - 1 + ty;
        bool row_ok = (rr >= 0) && (rr < HH);

        // W tile: 32 oc x 128B (256 chunks)
        {
            int o = tid >> 3, cc = tid & 7;
            cp_async16(smb + OSM_WH + o * PADB + cc * 16, g_woh16 + k * 2048 + o * 64 + cc * 8);
        }
        // A tile: 128 px rows of 128B fp16, shifted by (rr, tx-1)
#pragma unroll
        for (int j = 0; j < 4; ++j) {
            int idx2 = tid + j * 256;
            int px = idx2 >> 3, cc = idx2 & 7;
            int sc = px - 1 + tx;
            bool ok = row_ok && (sc >= 0) && (sc < WW);
            if (ok) {
                cp_async16(smb + OSM_A + px * PADB + cc * 16,
                           g_xh16 + (b * HW + rr * WW + sc) * 64 + cc * 8);
            } else {
                uint4 z = make_uint4(0, 0, 0, 0);
                *(uint4*)(sm + OSM_A + px * PADB + cc * 16) = z;
            }
        }
        cp_async_wait_all();
        __syncthreads();

        // mma: single pass x 4 k16-steps
#pragma unroll
        for (int ks = 0; ks < 4; ++ks) {
            uint32_t a0, a1, a2, a3;
            ldm_x4(a0, a1, a2, a3, smb + OSM_A + a_off + ks * 32);
#pragma unroll
            for (int nt = 0; nt < 4; ++nt) {
                uint32_t bf0, bf1;
                ldm_x2(bf0, bf1, smb + OSM_WH + b_offv[nt] + ks * 32);
                mma16816(acc[nt], a0, a1, a2, a3, bf0, bf1);
            }
        }
        __syncthreads();
    }

    int pbase = b * KT * HW + row * WW;
#pragma unroll
    for (int nt = 0; nt < 4; ++nt) {
        int oc = nt * 8 + (lane & 3) * 2;
#pragma unroll
        for (int half = 0; half < 2; ++half) {
            int px = wid * 16 + (lane >> 2) + half * 8;
#pragma unroll
            for (int e = 0; e < 2; ++e) {
                int o = oc + e;
                if (o >= 27) continue;
                float v = acc[nt][half * 2 + e] + __ldg(&boff[o]);
                if (o < 18) {
                    int q = o >> 1;
                    if ((o & 1) == 0) g_offy[pbase + q * HW + px] = v;
                    else              g_offx[pbase + q * HW + px] = v;
                } else {
                    g_mask[pbase + (o - 18) * HW + px] = 1.0f / (1.0f + __expf(-v));
                }
            }
        }
    }
}

// ---------------- main: homogeneous 8-warp, double-buffered, fp16 single-pass W ----------------
// 256 threads; warp w: px quarter (w&3)*32 (2 m-tiles), oc half (w>>2)*32 (4 n-tiles).
// Per tap: issue half gather LDGs -> mma 2 k-steps -> convert/store -> second half -> 1 barrier.
#define SM_A0    0
#define SM_A1    18432
#define SM_W0    36864
#define SM_W1    46080
#define SM_CW    55296
#define SM_CA    73728
#define SM_TOTAL 92160

__device__ __forceinline__ void issue_w(uint32_t wdst, const __half* wh, int tid) {
#pragma unroll
    for (int j = 0; j < 2; ++j) {
        int idx2 = tid + j * 256;
        int o = idx2 >> 3, cc = idx2 & 7;
        cp_async16(wdst + o * PADB + cc * 16, wh + o * 64 + cc * 8);
    }
}

__device__ __forceinline__ void gather_load(const uint2* __restrict__ xh,
                                            const int4* __restrict__ ca,
                                            int k, int r0, int q, int sub, uint2* L) {
#pragma unroll
    for (int rr = 0; rr < 4; ++rr) {
        int px = (r0 + rr) * 16 + sub;
        int4 av = ca[k * 128 + px];
        L[rr * 4 + 0] = xh[av.x + q];
        L[rr * 4 + 1] = xh[av.y + q];
        L[rr * 4 + 2] = xh[av.z + q];
        L[rr * 4 + 3] = xh[av.w + q];
    }
}

__device__ __forceinline__ void gather_store(const float4* __restrict__ cwf,
                                             int k, int r0, int q, int sub,
                                             const uint2* L, char* adst) {
#pragma unroll
    for (int rr = 0; rr < 4; ++rr) {
        int px = (r0 + rr) * 16 + sub;
        float4 wv = cwf[k * 128 + px];
        uint2 r00 = L[rr * 4 + 0];
        uint2 r01 = L[rr * 4 + 1];
        uint2 r10 = L[rr * 4 + 2];
        uint2 r11 = L[rr * 4 + 3];
        float2 c00a = __half22float2(*(const __half2*)&r00.x);
        float2 c00b = __half22float2(*(const __half2*)&r00.y);
        float2 c01a = __half22float2(*(const __half2*)&r01.x);
        float2 c01b = __half22float2(*(const __half2*)&r01.y);
        float2 c10a = __half22float2(*(const __half2*)&r10.x);
        float2 c10b = __half22float2(*(const __half2*)&r10.y);
        float2 c11a = __half22float2(*(const __half2*)&r11.x);
        float2 c11b = __half22float2(*(const __half2*)&r11.y);
        float v0 = wv.x * c00a.x + wv.y * c01a.x + wv.z * c10a.x + wv.w * c11a.x;
        float v1 = wv.x * c00a.y + wv.y * c01a.y + wv.z * c10a.y + wv.w * c11a.y;
        float v2 = wv.x * c00b.x + wv.y * c01b.x + wv.z * c10b.x + wv.w * c11b.x;
        float v3 = wv.x * c00b.y + wv.y * c01b.y + wv.z * c10b.y + wv.w * c11b.y;
        __half2 h01 = __floats2half2_rn(v0, v1);
        __half2 h23 = __floats2half2_rn(v2, v3);
        uint2 hv;
        hv.x = *(uint32_t*)&h01;
        hv.y = *(uint32_t*)&h23;
        *(uint2*)(adst + px * PADB + q * 8) = hv;
    }
}

__device__ __forceinline__ void mma_two_ks(uint32_t ab, uint32_t wbb, int ks0,
                                           const uint32_t* a_off, const uint32_t* b_off,
                                           float acc[2][4][4]) {
#pragma unroll
    for (int ks = ks0; ks < ks0 + 2; ++ks) {
        uint32_t a[2][4];
#pragma unroll
        for (int mt = 0; mt < 2; ++mt)
            ldm_x4(a[mt][0], a[mt][1], a[mt][2], a[mt][3], ab + a_off[mt] + ks * 32);
#pragma unroll
        for (int nt = 0; nt < 4; ++nt) {
            uint32_t bf0, bf1;
            ldm_x2(bf0, bf1, wbb + b_off[nt] + ks * 32);
            mma16816(acc[0][nt], a[0][0], a[0][1], a[0][2], a[0][3], bf0, bf1);
            mma16816(acc[1][nt], a[1][0], a[1][1], a[1][2], a[1][3], bf0, bf1);
        }
    }
}

__global__ void __launch_bounds__(256, 2) dcn_main_kernel(float* __restrict__ out) {
    extern __shared__ char sm[];
    uint32_t smb = smem_u32(sm);
    int tid = threadIdx.x;
    int wid = tid >> 5;
    int lane = tid & 31;

    int b = blockIdx.x >> 7;
    int row = blockIdx.x & 127;

    int pxq = wid & 3;
    int ocg2 = wid >> 2;
    int q = tid & 15;
    int sub = tid >> 4;

    float acc[2][4][4];
#pragma unroll
    for (int mt = 0; mt < 2; ++mt)
#pragma unroll
        for (int nt = 0; nt < 4; ++nt)
#pragma unroll
            for (int i = 0; i < 4; ++i) acc[mt][nt][i] = 0.0f;

    float4* cwf = (float4*)(sm + SM_CW);
    int4* ca = (int4*)(sm + SM_CA);
    const uint2* xh = (const uint2*)(g_xh16 + b * (HW * CIN));

    // ---- coords for all 9 taps x 128 px ----
    for (int i = tid; i < KT * 128; i += 256) {
        int k = i >> 7;
        int px = i & 127;
        int off_idx = (b * KT + k) * HW + row * WW + px;
        float oy = g_offy[off_idx];
        float ox = g_offx[off_idx];
        float m  = g_mask[off_idx];
        float py = (float)(row - 1 + k / 3) + oy;
        float pxx = (float)(px - 1 + k % 3) + ox;
        float y0f = floorf(py), x0f = floorf(pxx);
        float ly = py - y0f, lx = pxx - x0f;
        int y0 = (int)y0f, x0 = (int)x0f;
        float vy0 = (y0 >= 0 && y0 < HH) ? 1.0f : 0.0f;
        float vy1 = (y0 + 1 >= 0 && y0 + 1 < HH) ? 1.0f : 0.0f;
        float vx0 = (x0 >= 0 && x0 < WW) ? 1.0f : 0.0f;
        float vx1 = (x0 + 1 >= 0 && x0 + 1 < WW) ? 1.0f : 0.0f;
        float4 wv;
        wv.x = (1.0f - ly) * (1.0f - lx) * m * vy0 * vx0;
        wv.y = (1.0f - ly) * lx * m * vy0 * vx1;
        wv.z = ly * (1.0f - lx) * m * vy1 * vx0;
        wv.w = ly * lx * m * vy1 * vx1;
        int yc0 = min(max(y0, 0), HH - 1);
        int yc1 = min(max(y0 + 1, 0), HH - 1);
        int xc0 = min(max(x0, 0), WW - 1);
        int xc1 = min(max(x0 + 1, 0), WW - 1);
        int4 av;
        av.x = (yc0 * WW + xc0) * 16;   // uint2 index: pos*128B/8B
        av.y = (yc0 * WW + xc1) * 16;
        av.z = (yc1 * WW + xc0) * 16;
        av.w = (yc1 * WW + xc1) * 16;
        cwf[i] = wv;
        ca[i] = av;
    }
    __syncthreads();

    uint32_t a_off[2];
#pragma unroll
    for (int mt = 0; mt < 2; ++mt)
        a_off[mt] = (uint32_t)((pxq * 32 + mt * 16 + (lane & 15)) * PADB + (lane >> 4) * 16);
    int l15 = lane & 15;
    uint32_t b_off[4];
#pragma unroll
    for (int nt = 0; nt < 4; ++nt)
        b_off[nt] = (uint32_t)((ocg2 * 32 + nt * 8 + (l15 & 7)) * PADB + ((l15 >> 3) & 1) * 16);

    // ---- prologue: fill buffer 0 with tap 0 ----
    issue_w(smb + SM_W0, g_wh16, tid);
    {
        uint2 L[16];
        gather_load(xh, ca, 0, 0, q, sub, L);
        gather_store(cwf, 0, 0, q, sub, L, sm + SM_A0);
        gather_load(xh, ca, 0, 4, q, sub, L);
        gather_store(cwf, 0, 4, q, sub, L, sm + SM_A0);
    }
    cp_async_wait_all();
    __syncthreads();

    // ---- pipelined main loop: 1 barrier per tap ----
#pragma unroll 1
    for (int k = 0; k < KT; ++k) {
        int cur = k & 1;
        uint32_t ab  = smb + (cur ? SM_A1 : SM_A0);
        uint32_t wbb = smb + (cur ? SM_W1 : SM_W0);
        char*  anx = sm + (cur ? SM_A0 : SM_A1);
        uint32_t wnx = smb + (cur ? SM_W0 : SM_W1);
        bool more = (k + 1 < KT);

        if (more) issue_w(wnx, g_wh16 + (k + 1) * 4096, tid);

        uint2 L[16];
        if (more) gather_load(xh, ca, k + 1, 0, q, sub, L);
        mma_two_ks(ab, wbb, 0, a_off, b_off, acc);
        if (more) gather_store(cwf, k + 1, 0, q, sub, L, anx);
        if (more) gather_load(xh, ca, k + 1, 4, q, sub, L);
        mma_two_ks(ab, wbb, 2, a_off, b_off, acc);
        if (more) gather_store(cwf, k + 1, 4, q, sub, L, anx);

        cp_async_wait_all();
        __syncthreads();
    }

    // ---- epilogue: bias + relu ----
    int obase = b * COUT * HW + row * WW;
#pragma unroll
    for (int mt = 0; mt < 2; ++mt) {
        int px = pxq * 32 + mt * 16 + (lane >> 2);
#pragma unroll
        for (int nt = 0; nt < 4; ++nt) {
            int oc = ocg2 * 32 + nt * 8 + (lane & 3) * 2;
            float b0 = __ldg(&g_bias2[oc]);
            float b1 = __ldg(&g_bias2[oc + 1]);
            out[obase + oc * HW + px]           = fmaxf(acc[mt][nt][0] + b0, 0.0f);
            out[obase + (oc + 1) * HW + px]     = fmaxf(acc[mt][nt][1] + b1, 0.0f);
            out[obase + oc * HW + px + 8]       = fmaxf(acc[mt][nt][2] + b0, 0.0f);
            out[obase + (oc + 1) * HW + px + 8] = fmaxf(acc[mt][nt][3] + b1, 0.0f);
        }
    }
}

// ---------------- launch ----------------
extern "C" void kernel_launch(void* const* d_in, const int* in_sizes, int n_in,
                              void* d_out, int out_size) {
    const float* x        = (const float*)d_in[0];
    const float* w_off    = (const float*)d_in[1];
    const float* b_off    = (const float*)d_in[2];
    const float* weight   = (const float*)d_in[3];
    const float* bias     = (const float*)d_in[4];
    const float* gamma    = (const float*)d_in[5];
    const float* beta     = (const float*)d_in[6];
    const float* run_mean = (const float*)d_in[7];
    const float* run_var  = (const float*)d_in[8];
    float* out = (float*)d_out;

    prep_kernel<<<(KT * CIN * COUT + 255) / 256, 256>>>(weight, bias, gamma, beta,
                                                        run_mean, run_var, w_off);

    transpose_kernel<<<BB * 2 * 512, 256>>>(x);

    cudaFuncSetAttribute(offset_mma_kernel,
                         cudaFuncAttributeMaxDynamicSharedMemorySize, OSM_TOTAL);
    offset_mma_kernel<<<BB * HH, 256, OSM_TOTAL>>>(b_off);

    cudaFuncSetAttribute(dcn_main_kernel,
                         cudaFuncAttributeMaxDynamicSharedMemorySize, SM_TOTAL);
    dcn_main_kernel<<<BB * HH, 256, SM_TOTAL>>>(out);
}

// round 16
// speedup vs baseline: 1.3451x; 1.3451x over previous
#include <cuda_runtime.h>
#include <cuda_fp16.h>
#include <math.h>
#include <stdint.h>

#define HH 128
#define WW 128
#define CIN 64
#define COUT 64
#define BB 2
#define KT 9
#define HW (HH*WW)
#define PADB 144   // padded A/W row stride in bytes (72 fp16) — conflict-free ldmatrix

// ---------------- scratch (device globals; no allocation) ----------------
__device__ __align__(16) float g_offy[BB * KT * HW];
__device__ __align__(16) float g_offx[BB * KT * HW];
__device__ __align__(16) float g_mask[BB * KT * HW];
__device__ __align__(16) __half g_xh16[BB * HW * CIN];        // NHWC fp16
__device__ __align__(16) __half g_wh16[KT * COUT * CIN];      // main W [k][o][c] hi (BN folded)
__device__ __align__(16) __half g_wl16[KT * COUT * CIN];      // lo
__device__ __align__(16) __half g_woh16[KT * 32 * CIN];       // offset W [k][oc pad32][c] fp16
__device__ float g_bias2[COUT];

// ---------------- helpers ----------------
__device__ __forceinline__ uint32_t smem_u32(const void* p) {
    uint32_t a;
    asm("{ .reg .u64 t; cvta.to.shared.u64 t, %1; cvt.u32.u64 %0, t; }" : "=r"(a) : "l"(p));
    return a;
}
__device__ __forceinline__ void ldm_x4(uint32_t& r0, uint32_t& r1, uint32_t& r2, uint32_t& r3,
                                       uint32_t addr) {
    asm volatile("ldmatrix.sync.aligned.m8n8.x4.shared.b16 {%0,%1,%2,%3}, [%4];"
        : "=r"(r0), "=r"(r1), "=r"(r2), "=r"(r3) : "r"(addr));
}
__device__ __forceinline__ void ldm_x2(uint32_t& r0, uint32_t& r1, uint32_t addr) {
    asm volatile("ldmatrix.sync.aligned.m8n8.x2.shared.b16 {%0,%1}, [%2];"
        : "=r"(r0), "=r"(r1) : "r"(addr));
}
__device__ __forceinline__ void mma16816(float* d,
                                         uint32_t a0, uint32_t a1, uint32_t a2, uint32_t a3,
                                         uint32_t b0, uint32_t b1) {
    asm volatile(
        "mma.sync.aligned.m16n8k16.row.col.f32.f16.f16.f32 "
        "{%0,%1,%2,%3}, {%4,%5,%6,%7}, {%8,%9}, {%0,%1,%2,%3};"
        : "+f"(d[0]), "+f"(d[1]), "+f"(d[2]), "+f"(d[3])
        : "r"(a0), "r"(a1), "r"(a2), "r"(a3), "r"(b0), "r"(b1));
}
__device__ __forceinline__ void cp_async16(uint32_t dst, const void* src) {
    asm volatile(
        "{ .reg .u64 g; cvta.to.global.u64 g, %1;\n\t"
        "cp.async.ca.shared.global [%0], [g], 16; }"
        :: "r"(dst), "l"(src) : "memory");
}
__device__ __forceinline__ void cp_async_wait_all() {
    asm volatile("cp.async.commit_group;\n\tcp.async.wait_group 0;" ::: "memory");
}

// ---------------- prep: fold BN; fp16 weight tiles ----------------
__global__ void prep_kernel(const float* __restrict__ weight,
                            const float* __restrict__ bias,
                            const float* __restrict__ gamma,
                            const float* __restrict__ beta,
                            const float* __restrict__ run_mean,
                            const float* __restrict__ run_var,
                            const float* __restrict__ w_off) {
    int idx = blockIdx.x * blockDim.x + threadIdx.x;
    if (idx < COUT) {
        float inv = gamma[idx] * rsqrtf(run_var[idx] + 1e-5f);
        g_bias2[idx] = (bias[idx] - run_mean[idx]) * inv + beta[idx];
    }
    if (idx < KT * CIN * COUT) {
        int k = idx >> 12;
        int c = (idx >> 6) & 63;
        int o = idx & 63;
        float inv = gamma[o] * rsqrtf(run_var[o] + 1e-5f);
        float val = weight[(o * CIN + c) * KT + k] * inv;
        __half hi = __float2half_rn(val);
        __half lo = __float2half_rn(val - __half2float(hi));
        g_wh16[k * 4096 + o * 64 + c] = hi;
        g_wl16[k * 4096 + o * 64 + c] = lo;
    }
    if (idx < KT * 32 * CIN) {
        int k = idx >> 11;
        int o = (idx >> 6) & 31;
        int c = idx & 63;
        float val = (o < 27) ? w_off[(o * CIN + c) * KT + k] : 0.0f;
        g_woh16[idx] = __float2half_rn(val);
    }
}

// ---------------- transpose x: NCHW fp32 -> NHWC fp16 ----------------
__global__ void transpose_kernel(const float* __restrict__ x) {
    __shared__ float t[32][33];
    int bid = blockIdx.x;
    int ct = bid & 1;
    int pt = (bid >> 1) & 511;
    int b = bid >> 10;
    int c0 = ct * 32, p0 = pt * 32;
    int tid = threadIdx.x;

#pragma unroll
    for (int pass = 0; pass < 4; ++pass) {
        int cl = (tid >> 5) + pass * 8;
        t[cl][tid & 31] = x[(b * CIN + c0 + cl) * HW + p0 + (tid & 31)];
    }
    __syncthreads();
    int p = tid >> 3, cc = tid & 7;
    float4 v = make_float4(t[cc * 4 + 0][p], t[cc * 4 + 1][p],
                           t[cc * 4 + 2][p], t[cc * 4 + 3][p]);
    int base = (b * HW + p0 + p) * CIN + c0 + cc * 4;
    __half2 h01 = __floats2half2_rn(v.x, v.y);
    __half2 h23 = __floats2half2_rn(v.z, v.w);
    uint2 hv;
    hv.x = *(uint32_t*)&h01;
    hv.y = *(uint32_t*)&h23;
    *(uint2*)&g_xh16[base] = hv;
}

// ---------------- offset conv as mma GEMM (fp16, single-pass W, double-buffered) ----------------
#define OSM_A0    0
#define OSM_A1    18432
#define OSM_W0    36864
#define OSM_W1    41472
#define OSM_TOTAL 46080

__global__ void __launch_bounds__(256) offset_mma_kernel(const float* __restrict__ boff) {
    extern __shared__ char sm[];
    uint32_t smb = smem_u32(sm);
    int tid = threadIdx.x;
    int wid = tid >> 5;
    int lane = tid & 31;

    int b = blockIdx.x >> 7;
    int row = blockIdx.x & 127;

    float acc[4][4];
#pragma unroll
    for (int nt = 0; nt < 4; ++nt)
#pragma unroll
        for (int i = 0; i < 4; ++i) acc[nt][i] = 0.0f;

    uint32_t a_off = (uint32_t)((wid * 16 + (lane & 15)) * PADB + (lane >> 4) * 16);
    int l15 = lane & 15;
    uint32_t b_offv[4];
#pragma unroll
    for (int nt = 0; nt < 4; ++nt)
        b_offv[nt] = (uint32_t)((nt * 8 + (l15 & 7)) * PADB + ((l15 >> 3) & 1) * 16);

    // issue all cp.async (+ zero stores) for tap k into buffer buf
    auto issue_tap = [&](int k, int buf) {
        int ty = k / 3, tx = k % 3;
        int rr = row - 1 + ty;
        bool row_ok = (rr >= 0) && (rr < HH);
        uint32_t abase = smb + (buf ? OSM_A1 : OSM_A0);
        uint32_t wbase = smb + (buf ? OSM_W1 : OSM_W0);
        char* azero = sm + (buf ? OSM_A1 : OSM_A0);
        {
            int o = tid >> 3, cc = tid & 7;
            cp_async16(wbase + o * PADB + cc * 16, g_woh16 + k * 2048 + o * 64 + cc * 8);
        }
#pragma unroll
        for (int j = 0; j < 4; ++j) {
            int idx2 = tid + j * 256;
            int px = idx2 >> 3, cc = idx2 & 7;
            int sc = px - 1 + tx;
            bool ok = row_ok && (sc >= 0) && (sc < WW);
            if (ok) {
                cp_async16(abase + px * PADB + cc * 16,
                           g_xh16 + (b * HW + rr * WW + sc) * 64 + cc * 8);
            } else {
                *(uint4*)(azero + px * PADB + cc * 16) = make_uint4(0, 0, 0, 0);
            }
        }
    };

    // prologue: tap 0 into buffer 0
    issue_tap(0, 0);
    cp_async_wait_all();
    __syncthreads();

#pragma unroll 1
    for (int k = 0; k < KT; ++k) {
        int cur = k & 1;
        bool more = (k + 1 < KT);
        if (more) issue_tap(k + 1, cur ^ 1);

        uint32_t ab = smb + (cur ? OSM_A1 : OSM_A0);
        uint32_t wb = smb + (cur ? OSM_W1 : OSM_W0);
#pragma unroll
        for (int ks = 0; ks < 4; ++ks) {
            uint32_t a0, a1, a2, a3;
            ldm_x4(a0, a1, a2, a3, ab + a_off + ks * 32);
#pragma unroll
            for (int nt = 0; nt < 4; ++nt) {
                uint32_t bf0, bf1;
                ldm_x2(bf0, bf1, wb + b_offv[nt] + ks * 32);
                mma16816(acc[nt], a0, a1, a2, a3, bf0, bf1);
            }
        }

        if (more) {
            cp_async_wait_all();
            __syncthreads();
        }
    }

    int pbase = b * KT * HW + row * WW;
#pragma unroll
    for (int nt = 0; nt < 4; ++nt) {
        int oc = nt * 8 + (lane & 3) * 2;
#pragma unroll
        for (int half = 0; half < 2; ++half) {
            int px = wid * 16 + (lane >> 2) + half * 8;
#pragma unroll
            for (int e = 0; e < 2; ++e) {
                int o = oc + e;
                if (o >= 27) continue;
                float v = acc[nt][half * 2 + e] + __ldg(&boff[o]);
                if (o < 18) {
                    int q = o >> 1;
                    if ((o & 1) == 0) g_offy[pbase + q * HW + px] = v;
                    else              g_offx[pbase + q * HW + px] = v;
                } else {
                    g_mask[pbase + (o - 18) * HW + px] = 1.0f / (1.0f + __expf(-v));
                }
            }
        }
    }
}

// ---------------- main: homogeneous 8-warp, double-buffered, fp16 2-pass W ----------------
// 256 threads; warp w: px quarter (w&3)*32 (2 m-tiles), oc half (w>>2)*32 (4 n-tiles).
// Per tap: issue half gather LDGs -> mma 2 k-steps -> convert/store -> second half -> 1 barrier.
#define SM_A0    0
#define SM_A1    18432
#define SM_W0    36864        // hi at +0, lo at +9216
#define SM_W1    55296
#define SM_CW    73728
#define SM_CA    92160
#define SM_TOTAL 110592

__device__ __forceinline__ void issue_w(uint32_t wdst, const __half* wh, const __half* wl,
                                        int tid) {
#pragma unroll
    for (int j = 0; j < 2; ++j) {
        int idx2 = tid + j * 256;
        int o = idx2 >> 3, cc = idx2 & 7;
        cp_async16(wdst + o * PADB + cc * 16, wh + o * 64 + cc * 8);
        cp_async16(wdst + 9216 + o * PADB + cc * 16, wl + o * 64 + cc * 8);
    }
}

__device__ __forceinline__ void gather_load(const uint2* __restrict__ xh,
                                            const int4* __restrict__ ca,
                                            int k, int r0, int q, int sub, uint2* L) {
#pragma unroll
    for (int rr = 0; rr < 4; ++rr) {
        int px = (r0 + rr) * 16 + sub;
        int4 av = ca[k * 128 + px];
        L[rr * 4 + 0] = xh[av.x + q];
        L[rr * 4 + 1] = xh[av.y + q];
        L[rr * 4 + 2] = xh[av.z + q];
        L[rr * 4 + 3] = xh[av.w + q];
    }
}

__device__ __forceinline__ void gather_store(const float4* __restrict__ cwf,
                                             int k, int r0, int q, int sub,
                                             const uint2* L, char* adst) {
#pragma unroll
    for (int rr = 0; rr < 4; ++rr) {
        int px = (r0 + rr) * 16 + sub;
        float4 wv = cwf[k * 128 + px];
        uint2 r00 = L[rr * 4 + 0];
        uint2 r01 = L[rr * 4 + 1];
        uint2 r10 = L[rr * 4 + 2];
        uint2 r11 = L[rr * 4 + 3];
        float2 c00a = __half22float2(*(const __half2*)&r00.x);
        float2 c00b = __half22float2(*(const __half2*)&r00.y);
        float2 c01a = __half22float2(*(const __half2*)&r01.x);
        float2 c01b = __half22float2(*(const __half2*)&r01.y);
        float2 c10a = __half22float2(*(const __half2*)&r10.x);
        float2 c10b = __half22float2(*(const __half2*)&r10.y);
        float2 c11a = __half22float2(*(const __half2*)&r11.x);
        float2 c11b = __half22float2(*(const __half2*)&r11.y);
        float v0 = wv.x * c00a.x + wv.y * c01a.x + wv.z * c10a.x + wv.w * c11a.x;
        float v1 = wv.x * c00a.y + wv.y * c01a.y + wv.z * c10a.y + wv.w * c11a.y;
        float v2 = wv.x * c00b.x + wv.y * c01b.x + wv.z * c10b.x + wv.w * c11b.x;
        float v3 = wv.x * c00b.y + wv.y * c01b.y + wv.z * c10b.y + wv.w * c11b.y;
        __half2 h01 = __floats2half2_rn(v0, v1);
        __half2 h23 = __floats2half2_rn(v2, v3);
        uint2 hv;
        hv.x = *(uint32_t*)&h01;
        hv.y = *(uint32_t*)&h23;
        *(uint2*)(adst + px * PADB + q * 8) = hv;
    }
}

__device__ __forceinline__ void mma_two_ks(uint32_t ab, uint32_t wbb, int ks0,
                                           const uint32_t* a_off, const uint32_t* b_off,
                                           float acc[2][4][4]) {
#pragma unroll
    for (int ks = ks0; ks < ks0 + 2; ++ks) {
        uint32_t a[2][4];
#pragma unroll
        for (int mt = 0; mt < 2; ++mt)
            ldm_x4(a[mt][0], a[mt][1], a[mt][2], a[mt][3], ab + a_off[mt] + ks * 32);
#pragma unroll
        for (int pass = 0; pass < 2; ++pass) {
            uint32_t wb = wbb + pass * 9216;
#pragma unroll
            for (int nt = 0; nt < 4; ++nt) {
                uint32_t bf0, bf1;
                ldm_x2(bf0, bf1, wb + b_off[nt] + ks * 32);
                mma16816(acc[0][nt], a[0][0], a[0][1], a[0][2], a[0][3], bf0, bf1);
                mma16816(acc[1][nt], a[1][0], a[1][1], a[1][2], a[1][3], bf0, bf1);
            }
        }
    }
}

__global__ void __launch_bounds__(256, 2) dcn_main_kernel(float* __restrict__ out) {
    extern __shared__ char sm[];
    uint32_t smb = smem_u32(sm);
    int tid = threadIdx.x;
    int wid = tid >> 5;
    int lane = tid & 31;

    int b = blockIdx.x >> 7;
    int row = blockIdx.x & 127;

    int pxq = wid & 3;
    int ocg2 = wid >> 2;
    int q = tid & 15;
    int sub = tid >> 4;

    float acc[2][4][4];
#pragma unroll
    for (int mt = 0; mt < 2; ++mt)
#pragma unroll
        for (int nt = 0; nt < 4; ++nt)
#pragma unroll
            for (int i = 0; i < 4; ++i) acc[mt][nt][i] = 0.0f;

    float4* cwf = (float4*)(sm + SM_CW);
    int4* ca = (int4*)(sm + SM_CA);
    const uint2* xh = (const uint2*)(g_xh16 + b * (HW * CIN));

    // ---- coords for all 9 taps x 128 px ----
    for (int i = tid; i < KT * 128; i += 256) {
        int k = i >> 7;
        int px = i & 127;
        int off_idx = (b * KT + k) * HW + row * WW + px;
        float oy = g_offy[off_idx];
        float ox = g_offx[off_idx];
        float m  = g_mask[off_idx];
        float py = (float)(row - 1 + k / 3) + oy;
        float pxx = (float)(px - 1 + k % 3) + ox;
        float y0f = floorf(py), x0f = floorf(pxx);
        float ly = py - y0f, lx = pxx - x0f;
        int y0 = (int)y0f, x0 = (int)x0f;
        float vy0 = (y0 >= 0 && y0 < HH) ? 1.0f : 0.0f;
        float vy1 = (y0 + 1 >= 0 && y0 + 1 < HH) ? 1.0f : 0.0f;
        float vx0 = (x0 >= 0 && x0 < WW) ? 1.0f : 0.0f;
        float vx1 = (x0 + 1 >= 0 && x0 + 1 < WW) ? 1.0f : 0.0f;
        float4 wv;
        wv.x = (1.0f - ly) * (1.0f - lx) * m * vy0 * vx0;
        wv.y = (1.0f - ly) * lx * m * vy0 * vx1;
        wv.z = ly * (1.0f - lx) * m * vy1 * vx0;
        wv.w = ly * lx * m * vy1 * vx1;
        int yc0 = min(max(y0, 0), HH - 1);
        int yc1 = min(max(y0 + 1, 0), HH - 1);
        int xc0 = min(max(x0, 0), WW - 1);
        int xc1 = min(max(x0 + 1, 0), WW - 1);
        int4 av;
        av.x = (yc0 * WW + xc0) * 16;   // uint2 index: pos*128B/8B
        av.y = (yc0 * WW + xc1) * 16;
        av.z = (yc1 * WW + xc0) * 16;
        av.w = (yc1 * WW + xc1) * 16;
        cwf[i] = wv;
        ca[i] = av;
    }
    __syncthreads();

    uint32_t a_off[2];
#pragma unroll
    for (int mt = 0; mt < 2; ++mt)
        a_off[mt] = (uint32_t)((pxq * 32 + mt * 16 + (lane & 15)) * PADB + (lane >> 4) * 16);
    int l15 = lane & 15;
    uint32_t b_off[4];
#pragma unroll
    for (int nt = 0; nt < 4; ++nt)
        b_off[nt] = (uint32_t)((ocg2 * 32 + nt * 8 + (l15 & 7)) * PADB + ((l15 >> 3) & 1) * 16);

    // ---- prologue: fill buffer 0 with tap 0 ----
    issue_w(smb + SM_W0, g_wh16, g_wl16, tid);
    {
        uint2 L[16];
        gather_load(xh, ca, 0, 0, q, sub, L);
        gather_store(cwf, 0, 0, q, sub, L, sm + SM_A0);
        gather_load(xh, ca, 0, 4, q, sub, L);
        gather_store(cwf, 0, 4, q, sub, L, sm + SM_A0);
    }
    cp_async_wait_all();
    __syncthreads();

    // ---- pipelined main loop: 1 barrier per tap ----
#pragma unroll 1
    for (int k = 0; k < KT; ++k) {
        int cur = k & 1;
        uint32_t ab  = smb + (cur ? SM_A1 : SM_A0);
        uint32_t wbb = smb + (cur ? SM_W1 : SM_W0);
        char*  anx = sm + (cur ? SM_A0 : SM_A1);
        uint32_t wnx = smb + (cur ? SM_W0 : SM_W1);
        bool more = (k + 1 < KT);

        if (more) issue_w(wnx, g_wh16 + (k + 1) * 4096, g_wl16 + (k + 1) * 4096, tid);

        uint2 L[16];
        if (more) gather_load(xh, ca, k + 1, 0, q, sub, L);
        mma_two_ks(ab, wbb, 0, a_off, b_off, acc);
        if (more) gather_store(cwf, k + 1, 0, q, sub, L, anx);
        if (more) gather_load(xh, ca, k + 1, 4, q, sub, L);
        mma_two_ks(ab, wbb, 2, a_off, b_off, acc);
        if (more) gather_store(cwf, k + 1, 4, q, sub, L, anx);

        cp_async_wait_all();
        __syncthreads();
    }

    // ---- epilogue: bias + relu ----
    int obase = b * COUT * HW + row * WW;
#pragma unroll
    for (int mt = 0; mt < 2; ++mt) {
        int px = pxq * 32 + mt * 16 + (lane >> 2);
#pragma unroll
        for (int nt = 0; nt < 4; ++nt) {
            int oc = ocg2 * 32 + nt * 8 + (lane & 3) * 2;
            float b0 = __ldg(&g_bias2[oc]);
            float b1 = __ldg(&g_bias2[oc + 1]);
            out[obase + oc * HW + px]           = fmaxf(acc[mt][nt][0] + b0, 0.0f);
            out[obase + (oc + 1) * HW + px]     = fmaxf(acc[mt][nt][1] + b1, 0.0f);
            out[obase + oc * HW + px + 8]       = fmaxf(acc[mt][nt][2] + b0, 0.0f);
            out[obase + (oc + 1) * HW + px + 8] = fmaxf(acc[mt][nt][3] + b1, 0.0f);
        }
    }
}

// ---------------- launch ----------------
extern "C" void kernel_launch(void* const* d_in, const int* in_sizes, int n_in,
                              void* d_out, int out_size) {
    const float* x        = (const float*)d_in[0];
    const float* w_off    = (const float*)d_in[1];
    const float* b_off    = (const float*)d_in[2];
    const float* weight   = (const float*)d_in[3];
    const float* bias     = (const float*)d_in[4];
    const float* gamma    = (const float*)d_in[5];
    const float* beta     = (const float*)d_in[6];
    const float* run_mean = (const float*)d_in[7];
    const float* run_var  = (const float*)d_in[8];
    float* out = (float*)d_out;

    prep_kernel<<<(KT * CIN * COUT + 255) / 256, 256>>>(weight, bias, gamma, beta,
                                                        run_mean, run_var, w_off);

    transpose_kernel<<<BB * 2 * 512, 256>>>(x);

    cudaFuncSetAttribute(offset_mma_kernel,
                         cudaFuncAttributeMaxDynamicSharedMemorySize, OSM_TOTAL);
    offset_mma_kernel<<<BB * HH, 256, OSM_TOTAL>>>(b_off);

    cudaFuncSetAttribute(dcn_main_kernel,
                         cudaFuncAttributeMaxDynamicSharedMemorySize, SM_TOTAL);
    dcn_main_kernel<<<BB * HH, 256, SM_TOTAL>>>(out);
}

// round 17
// speedup vs baseline: 1.5429x; 1.1470x over previous
#include <cuda_runtime.h>
#include <cuda_fp16.h>
#include <math.h>
#include <stdint.h>

#define HH 128
#define WW 128
#define CIN 64
#define COUT 64
#define BB 2
#define KT 9
#define HW (HH*WW)
#define PADB 144   // padded A/W row stride in bytes (72 fp16) — conflict-free ldmatrix

// ---------------- scratch (device globals; no allocation) ----------------
__device__ __align__(16) float g_offy[BB * KT * HW];
__device__ __align__(16) float g_offx[BB * KT * HW];
__device__ __align__(16) float g_mask[BB * KT * HW];
__device__ __align__(16) __half g_xh16[BB * HW * CIN];        // NHWC fp16
__device__ __align__(16) __half g_wh16[KT * COUT * CIN];      // main W [k][o][c] hi (BN folded)
__device__ __align__(16) __half g_wl16[KT * COUT * CIN];      // lo
__device__ __align__(16) __half g_woh16[KT * 32 * CIN];       // offset W [k][oc pad32][c] fp16
__device__ float g_bias2[COUT];

// ---------------- helpers ----------------
__device__ __forceinline__ uint32_t smem_u32(const void* p) {
    uint32_t a;
    asm("{ .reg .u64 t; cvta.to.shared.u64 t, %1; cvt.u32.u64 %0, t; }" : "=r"(a) : "l"(p));
    return a;
}
__device__ __forceinline__ void ldm_x4(uint32_t& r0, uint32_t& r1, uint32_t& r2, uint32_t& r3,
                                       uint32_t addr) {
    asm volatile("ldmatrix.sync.aligned.m8n8.x4.shared.b16 {%0,%1,%2,%3}, [%4];"
        : "=r"(r0), "=r"(r1), "=r"(r2), "=r"(r3) : "r"(addr));
}
__device__ __forceinline__ void ldm_x2(uint32_t& r0, uint32_t& r1, uint32_t addr) {
    asm volatile("ldmatrix.sync.aligned.m8n8.x2.shared.b16 {%0,%1}, [%2];"
        : "=r"(r0), "=r"(r1) : "r"(addr));
}
__device__ __forceinline__ void mma16816(float* d,
                                         uint32_t a0, uint32_t a1, uint32_t a2, uint32_t a3,
                                         uint32_t b0, uint32_t b1) {
    asm volatile(
        "mma.sync.aligned.m16n8k16.row.col.f32.f16.f16.f32 "
        "{%0,%1,%2,%3}, {%4,%5,%6,%7}, {%8,%9}, {%0,%1,%2,%3};"
        : "+f"(d[0]), "+f"(d[1]), "+f"(d[2]), "+f"(d[3])
        : "r"(a0), "r"(a1), "r"(a2), "r"(a3), "r"(b0), "r"(b1));
}
__device__ __forceinline__ void cp_async16(uint32_t dst, const void* src) {
    asm volatile(
        "{ .reg .u64 g; cvta.to.global.u64 g, %1;\n\t"
        "cp.async.ca.shared.global [%0], [g], 16; }"
        :: "r"(dst), "l"(src) : "memory");
}
__device__ __forceinline__ void cp_async_wait_all() {
    asm volatile("cp.async.commit_group;\n\tcp.async.wait_group 0;" ::: "memory");
}

// ---------------- prep: fold BN; fp16 weight tiles (coalesced reads) ----------------
__global__ void prep_kernel(const float* __restrict__ weight,
                            const float* __restrict__ bias,
                            const float* __restrict__ gamma,
                            const float* __restrict__ beta,
                            const float* __restrict__ run_mean,
                            const float* __restrict__ run_var,
                            const float* __restrict__ w_off) {
    int idx = blockIdx.x * blockDim.x + threadIdx.x;
    if (idx < COUT) {
        float inv = gamma[idx] * rsqrtf(run_var[idx] + 1e-5f);
        g_bias2[idx] = (bias[idx] - run_mean[idx]) * inv + beta[idx];
    }
    if (idx < KT * CIN * COUT) {
        // enumerate the SOURCE linearly: weight[o][c][k] with k fastest
        int o = idx / 576;
        int rem = idx - o * 576;
        int c = rem / 9;
        int k = rem - c * 9;
        float inv = gamma[o] * rsqrtf(run_var[o] + 1e-5f);
        float val = weight[idx] * inv;
        __half hi = __float2half_rn(val);
        __half lo = __float2half_rn(val - __half2float(hi));
        g_wh16[k * 4096 + o * 64 + c] = hi;
        g_wl16[k * 4096 + o * 64 + c] = lo;
    }
    if (idx < KT * 32 * CIN) {
        // w_off[o][c][k] linear for o<27; pad rows 27..31 with zero
        int o = idx / 576;
        int rem = idx - o * 576;
        int c = rem / 9;
        int k = rem - c * 9;
        float val = (o < 27) ? w_off[idx] : 0.0f;
        g_woh16[k * 2048 + o * 64 + c] = __float2half_rn(val);
    }
}

// ---------------- transpose x: NCHW fp32 -> NHWC fp16 ----------------
__global__ void transpose_kernel(const float* __restrict__ x) {
    __shared__ float t[32][33];
    int bid = blockIdx.x;
    int ct = bid & 1;
    int pt = (bid >> 1) & 511;
    int b = bid >> 10;
    int c0 = ct * 32, p0 = pt * 32;
    int tid = threadIdx.x;

#pragma unroll
    for (int pass = 0; pass < 4; ++pass) {
        int cl = (tid >> 5) + pass * 8;
        t[cl][tid & 31] = x[(b * CIN + c0 + cl) * HW + p0 + (tid & 31)];
    }
    __syncthreads();
    int p = tid >> 3, cc = tid & 7;
    float4 v = make_float4(t[cc * 4 + 0][p], t[cc * 4 + 1][p],
                           t[cc * 4 + 2][p], t[cc * 4 + 3][p]);
    int base = (b * HW + p0 + p) * CIN + c0 + cc * 4;
    __half2 h01 = __floats2half2_rn(v.x, v.y);
    __half2 h23 = __floats2half2_rn(v.z, v.w);
    uint2 hv;
    hv.x = *(uint32_t*)&h01;
    hv.y = *(uint32_t*)&h23;
    *(uint2*)&g_xh16[base] = hv;
}

// ---------------- offset conv as mma GEMM (fp16, single-pass W) ----------------
#define OSM_A     0
#define OSM_WH    18432
#define OSM_TOTAL 23040

__global__ void __launch_bounds__(256) offset_mma_kernel(const float* __restrict__ boff) {
    extern __shared__ char sm[];
    uint32_t smb = smem_u32(sm);
    int tid = threadIdx.x;
    int wid = tid >> 5;
    int lane = tid & 31;

    int b = blockIdx.x >> 7;
    int row = blockIdx.x & 127;

    float acc[4][4];
#pragma unroll
    for (int nt = 0; nt < 4; ++nt)
#pragma unroll
        for (int i = 0; i < 4; ++i) acc[nt][i] = 0.0f;

    uint32_t a_off = (uint32_t)((wid * 16 + (lane & 15)) * PADB + (lane >> 4) * 16);
    int l15 = lane & 15;
    uint32_t b_offv[4];
#pragma unroll
    for (int nt = 0; nt < 4; ++nt)
        b_offv[nt] = (uint32_t)((nt * 8 + (l15 & 7)) * PADB + ((l15 >> 3) & 1) * 16);

#pragma unroll 1
    for (int k = 0; k < KT; ++k) {
        int ty = k / 3, tx = k % 3;
        int rr = row - 1 + ty;
        bool row_ok = (rr >= 0) && (rr < HH);

        // W tile: 32 oc x 128B (256 chunks)
        {
            int o = tid >> 3, cc = tid & 7;
            cp_async16(smb + OSM_WH + o * PADB + cc * 16, g_woh16 + k * 2048 + o * 64 + cc * 8);
        }
        // A tile: 128 px rows of 128B fp16, shifted by (rr, tx-1)
#pragma unroll
        for (int j = 0; j < 4; ++j) {
            int idx2 = tid + j * 256;
            int px = idx2 >> 3, cc = idx2 & 7;
            int sc = px - 1 + tx;
            bool ok = row_ok && (sc >= 0) && (sc < WW);
            if (ok) {
                cp_async16(smb + OSM_A + px * PADB + cc * 16,
                           g_xh16 + (b * HW + rr * WW + sc) * 64 + cc * 8);
            } else {
                uint4 z = make_uint4(0, 0, 0, 0);
                *(uint4*)(sm + OSM_A + px * PADB + cc * 16) = z;
            }
        }
        cp_async_wait_all();
        __syncthreads();

        // mma: single pass x 4 k16-steps
#pragma unroll
        for (int ks = 0; ks < 4; ++ks) {
            uint32_t a0, a1, a2, a3;
            ldm_x4(a0, a1, a2, a3, smb + OSM_A + a_off + ks * 32);
#pragma unroll
            for (int nt = 0; nt < 4; ++nt) {
                uint32_t bf0, bf1;
                ldm_x2(bf0, bf1, smb + OSM_WH + b_offv[nt] + ks * 32);
                mma16816(acc[nt], a0, a1, a2, a3, bf0, bf1);
            }
        }
        __syncthreads();
    }

    int pbase = b * KT * HW + row * WW;
#pragma unroll
    for (int nt = 0; nt < 4; ++nt) {
        int oc = nt * 8 + (lane & 3) * 2;
#pragma unroll
        for (int half = 0; half < 2; ++half) {
            int px = wid * 16 + (lane >> 2) + half * 8;
#pragma unroll
            for (int e = 0; e < 2; ++e) {
                int o = oc + e;
                if (o >= 27) continue;
                float v = acc[nt][half * 2 + e] + __ldg(&boff[o]);
                if (o < 18) {
                    int q = o >> 1;
                    if ((o & 1) == 0) g_offy[pbase + q * HW + px] = v;
                    else              g_offx[pbase + q * HW + px] = v;
                } else {
                    g_mask[pbase + (o - 18) * HW + px] = 1.0f / (1.0f + __expf(-v));
                }
            }
        }
    }
}

// ---------------- main: homogeneous 8-warp, double-buffered, fp16 2-pass W ----------------
// 256 threads; warp w: px quarter (w&3)*32 (2 m-tiles), oc half (w>>2)*32 (4 n-tiles).
// Per tap: issue half gather LDGs -> mma 2 k-steps -> convert/store -> second half -> 1 barrier.
#define SM_A0    0
#define SM_A1    18432
#define SM_W0    36864        // hi at +0, lo at +9216
#define SM_W1    55296
#define SM_CW    73728
#define SM_CA    92160
#define SM_TOTAL 110592

__device__ __forceinline__ void issue_w(uint32_t wdst, const __half* wh, const __half* wl,
                                        int tid) {
#pragma unroll
    for (int j = 0; j < 2; ++j) {
        int idx2 = tid + j * 256;
        int o = idx2 >> 3, cc = idx2 & 7;
        cp_async16(wdst + o * PADB + cc * 16, wh + o * 64 + cc * 8);
        cp_async16(wdst + 9216 + o * PADB + cc * 16, wl + o * 64 + cc * 8);
    }
}

__device__ __forceinline__ void gather_load(const uint2* __restrict__ xh,
                                            const int4* __restrict__ ca,
                                            int k, int r0, int q, int sub, uint2* L) {
#pragma unroll
    for (int rr = 0; rr < 4; ++rr) {
        int px = (r0 + rr) * 16 + sub;
        int4 av = ca[k * 128 + px];
        L[rr * 4 + 0] = xh[av.x + q];
        L[rr * 4 + 1] = xh[av.y + q];
        L[rr * 4 + 2] = xh[av.z + q];
        L[rr * 4 + 3] = xh[av.w + q];
    }
}

__device__ __forceinline__ void gather_store(const float4* __restrict__ cwf,
                                             int k, int r0, int q, int sub,
                                             const uint2* L, char* adst) {
#pragma unroll
    for (int rr = 0; rr < 4; ++rr) {
        int px = (r0 + rr) * 16 + sub;
        float4 wv = cwf[k * 128 + px];
        uint2 r00 = L[rr * 4 + 0];
        uint2 r01 = L[rr * 4 + 1];
        uint2 r10 = L[rr * 4 + 2];
        uint2 r11 = L[rr * 4 + 3];
        float2 c00a = __half22float2(*(const __half2*)&r00.x);
        float2 c00b = __half22float2(*(const __half2*)&r00.y);
        float2 c01a = __half22float2(*(const __half2*)&r01.x);
        float2 c01b = __half22float2(*(const __half2*)&r01.y);
        float2 c10a = __half22float2(*(const __half2*)&r10.x);
        float2 c10b = __half22float2(*(const __half2*)&r10.y);
        float2 c11a = __half22float2(*(const __half2*)&r11.x);
        float2 c11b = __half22float2(*(const __half2*)&r11.y);
        float v0 = wv.x * c00a.x + wv.y * c01a.x + wv.z * c10a.x + wv.w * c11a.x;
        float v1 = wv.x * c00a.y + wv.y * c01a.y + wv.z * c10a.y + wv.w * c11a.y;
        float v2 = wv.x * c00b.x + wv.y * c01b.x + wv.z * c10b.x + wv.w * c11b.x;
        float v3 = wv.x * c00b.y + wv.y * c01b.y + wv.z * c10b.y + wv.w * c11b.y;
        __half2 h01 = __floats2half2_rn(v0, v1);
        __half2 h23 = __floats2half2_rn(v2, v3);
        uint2 hv;
        hv.x = *(uint32_t*)&h01;
        hv.y = *(uint32_t*)&h23;
        *(uint2*)(adst + px * PADB + q * 8) = hv;
    }
}

__device__ __forceinline__ void mma_two_ks(uint32_t ab, uint32_t wbb, int ks0,
                                           const uint32_t* a_off, const uint32_t* b_off,
                                           float acc[2][4][4]) {
#pragma unroll
    for (int ks = ks0; ks < ks0 + 2; ++ks) {
        uint32_t a[2][4];
#pragma unroll
        for (int mt = 0; mt < 2; ++mt)
            ldm_x4(a[mt][0], a[mt][1], a[mt][2], a[mt][3], ab + a_off[mt] + ks * 32);
#pragma unroll
        for (int pass = 0; pass < 2; ++pass) {
            uint32_t wb = wbb + pass * 9216;
#pragma unroll
            for (int nt = 0; nt < 4; ++nt) {
                uint32_t bf0, bf1;
                ldm_x2(bf0, bf1, wb + b_off[nt] + ks * 32);
                mma16816(acc[0][nt], a[0][0], a[0][1], a[0][2], a[0][3], bf0, bf1);
                mma16816(acc[1][nt], a[1][0], a[1][1], a[1][2], a[1][3], bf0, bf1);
            }
        }
    }
}

__global__ void __launch_bounds__(256, 2) dcn_main_kernel(float* __restrict__ out) {
    extern __shared__ char sm[];
    uint32_t smb = smem_u32(sm);
    int tid = threadIdx.x;
    int wid = tid >> 5;
    int lane = tid & 31;

    int b = blockIdx.x >> 7;
    int row = blockIdx.x & 127;

    int pxq = wid & 3;
    int ocg2 = wid >> 2;
    int q = tid & 15;
    int sub = tid >> 4;

    float acc[2][4][4];
#pragma unroll
    for (int mt = 0; mt < 2; ++mt)
#pragma unroll
        for (int nt = 0; nt < 4; ++nt)
#pragma unroll
            for (int i = 0; i < 4; ++i) acc[mt][nt][i] = 0.0f;

    float4* cwf = (float4*)(sm + SM_CW);
    int4* ca = (int4*)(sm + SM_CA);
    const uint2* xh = (const uint2*)(g_xh16 + b * (HW * CIN));

    // ---- coords for all 9 taps x 128 px ----
    for (int i = tid; i < KT * 128; i += 256) {
        int k = i >> 7;
        int px = i & 127;
        int off_idx = (b * KT + k) * HW + row * WW + px;
        float oy = g_offy[off_idx];
        float ox = g_offx[off_idx];
        float m  = g_mask[off_idx];
        float py = (float)(row - 1 + k / 3) + oy;
        float pxx = (float)(px - 1 + k % 3) + ox;
        float y0f = floorf(py), x0f = floorf(pxx);
        float ly = py - y0f, lx = pxx - x0f;
        int y0 = (int)y0f, x0 = (int)x0f;
        float vy0 = (y0 >= 0 && y0 < HH) ? 1.0f : 0.0f;
        float vy1 = (y0 + 1 >= 0 && y0 + 1 < HH) ? 1.0f : 0.0f;
        float vx0 = (x0 >= 0 && x0 < WW) ? 1.0f : 0.0f;
        float vx1 = (x0 + 1 >= 0 && x0 + 1 < WW) ? 1.0f : 0.0f;
        float4 wv;
        wv.x = (1.0f - ly) * (1.0f - lx) * m * vy0 * vx0;
        wv.y = (1.0f - ly) * lx * m * vy0 * vx1;
        wv.z = ly * (1.0f - lx) * m * vy1 * vx0;
        wv.w = ly * lx * m * vy1 * vx1;
        int yc0 = min(max(y0, 0), HH - 1);
        int yc1 = min(max(y0 + 1, 0), HH - 1);
        int xc0 = min(max(x0, 0), WW - 1);
        int xc1 = min(max(x0 + 1, 0), WW - 1);
        int4 av;
        av.x = (yc0 * WW + xc0) * 16;   // uint2 index: pos*128B/8B
        av.y = (yc0 * WW + xc1) * 16;
        av.z = (yc1 * WW + xc0) * 16;
        av.w = (yc1 * WW + xc1) * 16;
        cwf[i] = wv;
        ca[i] = av;
    }
    __syncthreads();

    uint32_t a_off[2];
#pragma unroll
    for (int mt = 0; mt < 2; ++mt)
        a_off[mt] = (uint32_t)((pxq * 32 + mt * 16 + (lane & 15)) * PADB + (lane >> 4) * 16);
    int l15 = lane & 15;
    uint32_t b_off[4];
#pragma unroll
    for (int nt = 0; nt < 4; ++nt)
        b_off[nt] = (uint32_t)((ocg2 * 32 + nt * 8 + (l15 & 7)) * PADB + ((l15 >> 3) & 1) * 16);

    // ---- prologue: fill buffer 0 with tap 0 ----
    issue_w(smb + SM_W0, g_wh16, g_wl16, tid);
    {
        uint2 L[16];
        gather_load(xh, ca, 0, 0, q, sub, L);
        gather_store(cwf, 0, 0, q, sub, L, sm + SM_A0);
        gather_load(xh, ca, 0, 4, q, sub, L);
        gather_store(cwf, 0, 4, q, sub, L, sm + SM_A0);
    }
    cp_async_wait_all();
    __syncthreads();

    // ---- pipelined main loop: 1 barrier per tap ----
#pragma unroll 1
    for (int k = 0; k < KT; ++k) {
        int cur = k & 1;
        uint32_t ab  = smb + (cur ? SM_A1 : SM_A0);
        uint32_t wbb = smb + (cur ? SM_W1 : SM_W0);
        char*  anx = sm + (cur ? SM_A0 : SM_A1);
        uint32_t wnx = smb + (cur ? SM_W0 : SM_W1);
        bool more = (k + 1 < KT);

        if (more) issue_w(wnx, g_wh16 + (k + 1) * 4096, g_wl16 + (k + 1) * 4096, tid);

        uint2 L[16];
        if (more) gather_load(xh, ca, k + 1, 0, q, sub, L);
        mma_two_ks(ab, wbb, 0, a_off, b_off, acc);
        if (more) gather_store(cwf, k + 1, 0, q, sub, L, anx);
        if (more) gather_load(xh, ca, k + 1, 4, q, sub, L);
        mma_two_ks(ab, wbb, 2, a_off, b_off, acc);
        if (more) gather_store(cwf, k + 1, 4, q, sub, L, anx);

        cp_async_wait_all();
        __syncthreads();
    }

    // ---- epilogue: bias + relu ----
    int obase = b * COUT * HW + row * WW;
#pragma unroll
    for (int mt = 0; mt < 2; ++mt) {
        int px = pxq * 32 + mt * 16 + (lane >> 2);
#pragma unroll
        for (int nt = 0; nt < 4; ++nt) {
            int oc = ocg2 * 32 + nt * 8 + (lane & 3) * 2;
            float b0 = __ldg(&g_bias2[oc]);
            float b1 = __ldg(&g_bias2[oc + 1]);
            out[obase + oc * HW + px]           = fmaxf(acc[mt][nt][0] + b0, 0.0f);
            out[obase + (oc + 1) * HW + px]     = fmaxf(acc[mt][nt][1] + b1, 0.0f);
            out[obase + oc * HW + px + 8]       = fmaxf(acc[mt][nt][2] + b0, 0.0f);
            out[obase + (oc + 1) * HW + px + 8] = fmaxf(acc[mt][nt][3] + b1, 0.0f);
        }
    }
}

// ---------------- launch ----------------
extern "C" void kernel_launch(void* const* d_in, const int* in_sizes, int n_in,
                              void* d_out, int out_size) {
    const float* x        = (const float*)d_in[0];
    const float* w_off    = (const float*)d_in[1];
    const float* b_off    = (const float*)d_in[2];
    const float* weight   = (const float*)d_in[3];
    const float* bias     = (const float*)d_in[4];
    const float* gamma    = (const float*)d_in[5];
    const float* beta     = (const float*)d_in[6];
    const float* run_mean = (const float*)d_in[7];
    const float* run_var  = (const float*)d_in[8];
    float* out = (float*)d_out;

    prep_kernel<<<(KT * CIN * COUT + 255) / 256, 256>>>(weight, bias, gamma, beta,
                                                        run_mean, run_var, w_off);

    transpose_kernel<<<BB * 2 * 512, 256>>>(x);

    cudaFuncSetAttribute(offset_mma_kernel,
                         cudaFuncAttributeMaxDynamicSharedMemorySize, OSM_TOTAL);
    offset_mma_kernel<<<BB * HH, 256, OSM_TOTAL>>>(b_off);

    cudaFuncSetAttribute(dcn_main_kernel,
                         cudaFuncAttributeMaxDynamicSharedMemorySize, SM_TOTAL);
    dcn_main_kernel<<<BB * HH, 256, SM_TOTAL>>>(out);
}